// round 2
// baseline (speedup 1.0000x reference)
#include <cuda_runtime.h>
#include <math.h>

// ------------------------------------------------------------------
// Scratch arena (device global; allocation in kernel_launch forbidden).
// Lifetime-aliased regions (sequential stream => disjoint lifetimes):
//   A [0        , 67108864) : h1 [32,128,128,128]  then d2 [32,128,128,128]
//   B [67108864 ,100663296) : h2 [32,256,64,64]    then d1 [32,256,64,64]
//   C [100663296,117440512) : h3 [32,512,32,32]
//   D [117440512,119537664) : ze [32,64,32,32]
//   E [119537664,121634816) : zq [32,64,32,32]
// ------------------------------------------------------------------
__device__ float g_arena[121634816];

__device__ float g_wt1[6144];      // conv1  K=48   x 128
__device__ float g_wt2[524288];    // conv2  K=2048 x 256
__device__ float g_wt3[2097152];   // conv3  K=4096 x 512
__device__ float g_wtp[32768];     // 1x1    K=512  x 64
__device__ float g_wtd1[262144];   // convT1 4 x (K=256  x 256)
__device__ float g_wtd2[524288];   // convT2 4 x (K=1024 x 128)
__device__ float g_vqpart[256];

// ------------------------------------------------------------------
// Weight transforms
// ------------------------------------------------------------------
// forward conv: w[co][ci][kh][kw] -> wt[ci*16+kh*4+kw][co]
__global__ void wt_fwd_k(const float* __restrict__ w, float* __restrict__ wt,
                         int Cout, int CK) {
    int idx = blockIdx.x * 256 + threadIdx.x;
    if (idx >= Cout * CK) return;
    int co = idx / CK;
    int k  = idx - co * CK;
    wt[k * Cout + co] = w[idx];
}

// transpose conv: w[i][o][kh][kw] -> wt[par][(i*4+dh*2+dw)][o]
// par = py*2+px ; kh = 2*dh+1-py ; kw = 2*dw+1-px
__global__ void wt_tr_k(const float* __restrict__ w, float* __restrict__ wt,
                        int Cin, int Cout) {
    int per = Cin * 4 * Cout;
    int total = 4 * per;
    int idx = blockIdx.x * 256 + threadIdx.x;
    if (idx >= total) return;
    int par  = idx / per;
    int rem  = idx - par * per;
    int kidx = rem / Cout;
    int o    = rem - kidx * Cout;
    int i  = kidx >> 2, dh = (kidx >> 1) & 1, dw = kidx & 1;
    int py = par >> 1, px = par & 1;
    int kh = 2 * dh + 1 - py;
    int kw = 2 * dw + 1 - px;
    wt[idx] = w[((i * Cout + o) * 4 + kh) * 4 + kw];
}

// ------------------------------------------------------------------
// Unified implicit GEMM: C[m][p] = sum_k wt[k][m] * B[k][p]
// MODE 0: stride-2 k4 p1 conv   (K = Cin*16)
// MODE 1: 1x1 conv              (K = Cin),  Hin=1, Win=HW
// MODE 2: transpose conv parity (K = Cin*4)
// ACT 0: none, 1: relu
// ------------------------------------------------------------------
struct GP {
    const float* x;
    const float* wt;
    const float* bias;
    float*       out;
    int Cin, Hin, Win;
    int M;               // Cout
    int Hout, Wout;      // full output dims (MODE 2 write)
    int K;
    int sHWo;            // log2(p-positions per image)
    int sW;              // log2(decode width): MODE0 -> Wout, MODE2 -> Wout/2
    int py, px;
};

template<int MODE, int ACT>
__global__ __launch_bounds__(256) void igemm(GP g) {
    __shared__ __align__(16) float As[16][64];
    __shared__ __align__(16) float Bs[16][64];
    const int t  = threadIdx.x;
    const int p0 = blockIdx.x * 64;
    const int m0 = blockIdx.y * 64;
    const int lc = t & 63, lr = t >> 6;
    const int tx = t & 15, ty = t >> 4;

    // fixed p for this thread's B-tile column
    const int pB   = p0 + lc;
    const int nB   = pB >> g.sHWo;
    const int remB = pB & ((1 << g.sHWo) - 1);
    const int hoB  = remB >> g.sW;
    const int woB  = remB & ((1 << g.sW) - 1);
    const float* __restrict__ xn =
        g.x + (size_t)nB * g.Cin * g.Hin * g.Win;

    float acc[4][4];
#pragma unroll
    for (int i = 0; i < 4; i++)
#pragma unroll
        for (int j = 0; j < 4; j++) acc[i][j] = 0.f;

    for (int k0 = 0; k0 < g.K; k0 += 16) {
#pragma unroll
        for (int j = 0; j < 4; j++) {
            int r = lr + 4 * j;
            As[r][lc] = g.wt[(size_t)(k0 + r) * g.M + m0 + lc];
        }
#pragma unroll
        for (int j = 0; j < 4; j++) {
            int r = lr + 4 * j;
            int k = k0 + r;
            float v = 0.f;
            if (MODE == 0) {
                int ci = k >> 4, kh = (k >> 2) & 3, kw = k & 3;
                int ih = 2 * hoB - 1 + kh;
                int iw = 2 * woB - 1 + kw;
                if ((unsigned)ih < (unsigned)g.Hin &&
                    (unsigned)iw < (unsigned)g.Win)
                    v = xn[(ci * g.Hin + ih) * g.Win + iw];
            } else if (MODE == 1) {
                v = xn[(size_t)k * g.Win + remB];
            } else {
                int ci = k >> 2, dh = (k >> 1) & 1, dw = k & 1;
                int ih = hoB + g.py - dh;
                int iw = woB + g.px - dw;
                if ((unsigned)ih < (unsigned)g.Hin &&
                    (unsigned)iw < (unsigned)g.Win)
                    v = xn[(ci * g.Hin + ih) * g.Win + iw];
            }
            Bs[r][lc] = v;
        }
        __syncthreads();
#pragma unroll
        for (int kk = 0; kk < 16; kk++) {
            float4 a4 = *(const float4*)&As[kk][ty * 4];
            float4 b4 = *(const float4*)&Bs[kk][tx * 4];
            float av[4] = {a4.x, a4.y, a4.z, a4.w};
            float bv[4] = {b4.x, b4.y, b4.z, b4.w};
#pragma unroll
            for (int i = 0; i < 4; i++)
#pragma unroll
                for (int j = 0; j < 4; j++)
                    acc[i][j] += av[i] * bv[j];
        }
        __syncthreads();
    }

    const int HWo = 1 << g.sHWo;
#pragma unroll
    for (int j = 0; j < 4; j++) {
        int p   = p0 + tx * 4 + j;
        int n   = p >> g.sHWo;
        int rem = p & (HWo - 1);
#pragma unroll
        for (int i = 0; i < 4; i++) {
            int m = m0 + ty * 4 + i;
            float v = acc[i][j] + g.bias[m];
            if (ACT == 1) v = fmaxf(v, 0.f);
            if (MODE == 2) {
                int ho = rem >> g.sW, wo = rem & ((1 << g.sW) - 1);
                int y  = 2 * ho + g.py;
                int xx = 2 * wo + g.px;
                g.out[(((size_t)n * g.M + m) * g.Hout + y) * g.Wout + xx] = v;
            } else {
                g.out[((size_t)n * g.M + m) * HWo + rem] = v;
            }
        }
    }
}

// ------------------------------------------------------------------
// VQ: per-position nearest code, write z_q, per-block loss partials
// ze/zq: [32][64][1024] (d stride 1024), emb: [512][64]
// ------------------------------------------------------------------
__global__ __launch_bounds__(128) void vq_kernel(
    const float* __restrict__ ze, const float* __restrict__ emb,
    float* __restrict__ zq, float* __restrict__ partial) {
    __shared__ float es[128 * 64];  // 32KB codebook chunk
    __shared__ float red[128];
    const int t   = threadIdx.x;
    const int pos = blockIdx.x * 128 + t;
    const int n   = pos >> 10;
    const int hw  = pos & 1023;

    float xv[64];
    const float* zp = ze + (size_t)n * 65536 + hw;
#pragma unroll
    for (int d = 0; d < 64; d++) xv[d] = zp[(size_t)d * 1024];

    float best = 3.0e38f;
    int bidx = 0;
    for (int c0 = 0; c0 < 512; c0 += 128) {
        __syncthreads();
        for (int i = t; i < 128 * 64; i += 128) es[i] = emb[c0 * 64 + i];
        __syncthreads();
        for (int c = 0; c < 128; c++) {
            float d2 = 0.f;
#pragma unroll
            for (int d = 0; d < 64; d++) {
                float df = xv[d] - es[c * 64 + d];
                d2 += df * df;
            }
            if (d2 < best) { best = d2; bidx = c0 + c; }
        }
    }
    // write z_q (gather chosen code from global)
    const float* e = emb + (size_t)bidx * 64;
    float* q = zq + (size_t)n * 65536 + hw;
#pragma unroll
    for (int d = 0; d < 64; d++) q[(size_t)d * 1024] = e[d];

    // deterministic block reduction of best-dist
    red[t] = best;
    __syncthreads();
    for (int s = 64; s > 0; s >>= 1) {
        if (t < s) red[t] += red[t + s];
        __syncthreads();
    }
    if (t == 0) partial[blockIdx.x] = red[0];
}

__global__ void vq_loss_kernel(const float* __restrict__ partial,
                               float* __restrict__ out_loss) {
    __shared__ float red[256];
    int t = threadIdx.x;
    red[t] = partial[t];
    __syncthreads();
    for (int s = 128; s > 0; s >>= 1) {
        if (t < s) red[t] += red[t + s];
        __syncthreads();
    }
    if (t == 0) out_loss[0] = red[0] * (2.0f / 2097152.0f);
}

// ------------------------------------------------------------------
// convT3 direct: d2[32,128,128,128] -> out[32,3,256,256], sigmoid
// block = one parity class row: blockDim.x=128 (x'), grid (1, y'=128, n*4+par)
// ------------------------------------------------------------------
__global__ __launch_bounds__(128) void convt3_kernel(
    const float* __restrict__ in, const float* __restrict__ w,
    const float* __restrict__ b, float* __restrict__ out) {
    __shared__ float ws[6144];  // [128][3][4][4]
    for (int i = threadIdx.x; i < 6144; i += 128) ws[i] = w[i];
    __syncthreads();

    const int xq = threadIdx.x;        // x' 0..127
    const int yq = blockIdx.y;         // y' 0..127
    const int z  = blockIdx.z;
    const int n  = z >> 2;
    const int py = (z >> 1) & 1, px = z & 1;

    float a0 = b[0], a1 = b[1], a2 = b[2];
    const float* xn = in + (size_t)n * 128 * 128 * 128;
    for (int i = 0; i < 128; i++) {
        const float* xi = xn + (size_t)i * 16384;
#pragma unroll
        for (int dh = 0; dh < 2; dh++) {
#pragma unroll
            for (int dw = 0; dw < 2; dw++) {
                int h  = yq + py - dh;
                int wv = xq + px - dw;
                if ((unsigned)h < 128u && (unsigned)wv < 128u) {
                    float xvv = xi[h * 128 + wv];
                    int kh = 2 * dh + 1 - py;
                    int kw = 2 * dw + 1 - px;
                    int base = i * 48 + kh * 4 + kw;
                    a0 += xvv * ws[base];
                    a1 += xvv * ws[base + 16];
                    a2 += xvv * ws[base + 32];
                }
            }
        }
    }
    int y  = 2 * yq + py;
    int xx = 2 * xq + px;
    size_t o = ((size_t)n * 3) * 65536 + (size_t)y * 256 + xx;
    out[o]           = 1.f / (1.f + expf(-a0));
    out[o + 65536]   = 1.f / (1.f + expf(-a1));
    out[o + 131072]  = 1.f / (1.f + expf(-a2));
}

// ------------------------------------------------------------------
// Launch
// ------------------------------------------------------------------
extern "C" void kernel_launch(void* const* d_in, const int* in_sizes, int n_in,
                              void* d_out, int out_size) {
    (void)in_sizes; (void)n_in; (void)out_size;
    const float* x   = (const float*)d_in[0];
    const float* ew1 = (const float*)d_in[1];
    const float* eb1 = (const float*)d_in[2];
    const float* ew2 = (const float*)d_in[3];
    const float* eb2 = (const float*)d_in[4];
    const float* ew3 = (const float*)d_in[5];
    const float* eb3 = (const float*)d_in[6];
    const float* pw  = (const float*)d_in[7];
    const float* pb  = (const float*)d_in[8];
    const float* emb = (const float*)d_in[9];
    const float* dw1 = (const float*)d_in[10];
    const float* db1 = (const float*)d_in[11];
    const float* dw2 = (const float*)d_in[12];
    const float* db2 = (const float*)d_in[13];
    const float* dw3 = (const float*)d_in[14];
    const float* db3 = (const float*)d_in[15];
    float* out = (float*)d_out;

    float *arena;
    float *wt1, *wt2, *wt3, *wtp, *wtd1, *wtd2, *part;
    cudaGetSymbolAddress((void**)&arena, g_arena);
    cudaGetSymbolAddress((void**)&wt1,  g_wt1);
    cudaGetSymbolAddress((void**)&wt2,  g_wt2);
    cudaGetSymbolAddress((void**)&wt3,  g_wt3);
    cudaGetSymbolAddress((void**)&wtp,  g_wtp);
    cudaGetSymbolAddress((void**)&wtd1, g_wtd1);
    cudaGetSymbolAddress((void**)&wtd2, g_wtd2);
    cudaGetSymbolAddress((void**)&part, g_vqpart);

    // lifetime-aliased carve-out
    float* h1  = arena;              // 67108864
    float* d2b = arena;              // reuses h1's region
    float* h2  = arena + 67108864;   // 33554432
    float* d1b = arena + 67108864;   // reuses h2's region
    float* h3  = arena + 100663296;  // 16777216
    float* ze  = arena + 117440512;  //  2097152
    float* zq  = arena + 119537664;  //  2097152

    // weight transforms
    wt_fwd_k<<<(128 * 48 + 255) / 256, 256>>>(ew1, wt1, 128, 48);
    wt_fwd_k<<<(256 * 2048 + 255) / 256, 256>>>(ew2, wt2, 256, 2048);
    wt_fwd_k<<<(512 * 4096 + 255) / 256, 256>>>(ew3, wt3, 512, 4096);
    wt_fwd_k<<<(64 * 512 + 255) / 256, 256>>>(pw, wtp, 64, 512);
    wt_tr_k<<<(262144 + 255) / 256, 256>>>(dw1, wtd1, 64, 256);
    wt_tr_k<<<(524288 + 255) / 256, 256>>>(dw2, wtd2, 256, 128);

    GP g;
    // conv1: x[32,3,256,256] -> h1[32,128,128,128]
    g.x = x; g.wt = wt1; g.bias = eb1; g.out = h1;
    g.Cin = 3; g.Hin = 256; g.Win = 256; g.M = 128;
    g.Hout = 128; g.Wout = 128; g.K = 48; g.sHWo = 14; g.sW = 7;
    g.py = 0; g.px = 0;
    igemm<0, 1><<<dim3(524288 / 64, 2), 256>>>(g);

    // conv2: h1 -> h2[32,256,64,64]
    g.x = h1; g.wt = wt2; g.bias = eb2; g.out = h2;
    g.Cin = 128; g.Hin = 128; g.Win = 128; g.M = 256;
    g.Hout = 64; g.Wout = 64; g.K = 2048; g.sHWo = 12; g.sW = 6;
    igemm<0, 1><<<dim3(131072 / 64, 4), 256>>>(g);

    // conv3: h2 -> h3[32,512,32,32]
    g.x = h2; g.wt = wt3; g.bias = eb3; g.out = h3;
    g.Cin = 256; g.Hin = 64; g.Win = 64; g.M = 512;
    g.Hout = 32; g.Wout = 32; g.K = 4096; g.sHWo = 10; g.sW = 5;
    igemm<0, 1><<<dim3(32768 / 64, 8), 256>>>(g);

    // pre-VQ 1x1: h3 -> ze[32,64,32,32]   (treat HW flat: Hin=1, Win=1024)
    g.x = h3; g.wt = wtp; g.bias = pb; g.out = ze;
    g.Cin = 512; g.Hin = 1; g.Win = 1024; g.M = 64;
    g.Hout = 32; g.Wout = 32; g.K = 512; g.sHWo = 10; g.sW = 0;
    igemm<1, 0><<<dim3(32768 / 64, 1), 256>>>(g);

    // VQ
    vq_kernel<<<256, 128>>>(ze, emb, zq, part);
    vq_loss_kernel<<<1, 256>>>(part, out + 6291456);

    // convT1: zq[32,64,32,32] -> d1[32,256,64,64]
    for (int par = 0; par < 4; par++) {
        g.x = zq; g.wt = wtd1 + (size_t)par * 256 * 256; g.bias = db1;
        g.out = d1b;
        g.Cin = 64; g.Hin = 32; g.Win = 32; g.M = 256;
        g.Hout = 64; g.Wout = 64; g.K = 256; g.sHWo = 10; g.sW = 5;
        g.py = par >> 1; g.px = par & 1;
        igemm<2, 1><<<dim3(32768 / 64, 4), 256>>>(g);
    }

    // convT2: d1 -> d2[32,128,128,128]
    for (int par = 0; par < 4; par++) {
        g.x = d1b; g.wt = wtd2 + (size_t)par * 1024 * 128; g.bias = db2;
        g.out = d2b;
        g.Cin = 256; g.Hin = 64; g.Win = 64; g.M = 128;
        g.Hout = 128; g.Wout = 128; g.K = 1024; g.sHWo = 12; g.sW = 6;
        g.py = par >> 1; g.px = par & 1;
        igemm<2, 1><<<dim3(131072 / 64, 2), 256>>>(g);
    }

    // convT3 direct: d2 -> out[32,3,256,256], sigmoid
    convt3_kernel<<<dim3(1, 128, 128), 128>>>(d2b, dw3, db3, out);
}